// round 1
// baseline (speedup 1.0000x reference)
#include <cuda_runtime.h>
#include <cuda_bf16.h>
#include <cstdint>

// Problem constants (shapes fixed by the dataset)
#define N_NODE   50000
#define N_EDGE   800000
#define F_IN     128
#define EDGE_DIM 16
#define HEADS    4
#define D_OUT    32
#define HD       (HEADS * D_OUT)   // 128

// ---------------- scratch (device globals; no runtime allocation) ----------
__device__ float g_xl [(size_t)N_NODE * HD];     // 25.6 MB
__device__ float g_xr [(size_t)N_NODE * HD];     // 25.6 MB
__device__ float g_exp[(size_t)N_EDGE * HEADS];  // 12.8 MB
__device__ float g_sum[(size_t)N_NODE * HEADS];  //  0.8 MB
__device__ float g_agg[(size_t)N_NODE * HD];     // 25.6 MB

// ---------------- zero init --------------------------------------------------
__global__ void zero_kernel(int n_agg, int n_sum) {
    int i = blockIdx.x * blockDim.x + threadIdx.x;
    if (i < n_agg) g_agg[i] = 0.f;
    if (i < n_sum) g_sum[i] = 0.f;
}

// ---------------- projection GEMM: x_l / x_r = nodes @ W ------------------
// C[M,128] = A[M,128] @ W[128,128], two weight matrices via blockIdx.y.
// 64x64 tile, BK=8, 256 threads, 4x4 microtile.
#define BM 64
#define BN 64
#define BK 8
__global__ __launch_bounds__(256) void gemm_kernel(
    const float* __restrict__ A,
    const float* __restrict__ Wl,
    const float* __restrict__ Wr,
    int M)
{
    const int byi = blockIdx.y;                 // 0..3
    const float* B = (byi < 2) ? Wl : Wr;
    float*       C = (byi < 2) ? g_xl : g_xr;
    const int cn0 = (byi & 1) * BN;             // column offset within 128
    const int rm0 = blockIdx.x * BM;

    __shared__ float As[BK][BM + 4];            // transposed, padded (row=272B, 16B aligned)
    __shared__ float Bs[BK][BN];

    float acc[4][4];
#pragma unroll
    for (int i = 0; i < 4; i++)
#pragma unroll
        for (int j = 0; j < 4; j++) acc[i][j] = 0.f;

    const int tid = threadIdx.x;
    const int tx = tid & 15;                    // col group
    const int ty = tid >> 4;                    // row group

    const int li = tid * 2;
    const int ar = li / BK, ak = li % BK;       // A load coords
    const int bk = li / BN, bj = li % BN;       // B load coords

    for (int k0 = 0; k0 < F_IN; k0 += BK) {
        float2 av = make_float2(0.f, 0.f);
        if (rm0 + ar < M)
            av = *(const float2*)&A[(size_t)(rm0 + ar) * F_IN + k0 + ak];
        As[ak][ar]     = av.x;
        As[ak + 1][ar] = av.y;
        float2 bv = *(const float2*)&B[(size_t)(k0 + bk) * HD + cn0 + bj];
        Bs[bk][bj]     = bv.x;
        Bs[bk][bj + 1] = bv.y;
        __syncthreads();
#pragma unroll
        for (int k = 0; k < BK; k++) {
            float4 ra = *(const float4*)&As[k][ty * 4];
            float4 rb = *(const float4*)&Bs[k][tx * 4];
            float a_[4] = {ra.x, ra.y, ra.z, ra.w};
            float b_[4] = {rb.x, rb.y, rb.z, rb.w};
#pragma unroll
            for (int i = 0; i < 4; i++)
#pragma unroll
                for (int j = 0; j < 4; j++)
                    acc[i][j] = fmaf(a_[i], b_[j], acc[i][j]);
        }
        __syncthreads();
    }
#pragma unroll
    for (int i = 0; i < 4; i++) {
        int r = rm0 + ty * 4 + i;
        if (r < M) {
            float4 v = make_float4(acc[i][0], acc[i][1], acc[i][2], acc[i][3]);
            *(float4*)&C[(size_t)r * HD + cn0 + tx * 4] = v;
        }
    }
}

// ---------------- edge score pass: logits -> exp, atomic sums --------------
// One warp per edge. Lane ln owns HD columns {ln, ln+32, ln+64, ln+96}
// => column 32*m + ln corresponds to head m, dim ln.
__global__ __launch_bounds__(256) void edge_score_kernel(
    const int*   __restrict__ snd,
    const int*   __restrict__ rcv,
    const float* __restrict__ eattr,
    const float* __restrict__ We,
    const float* __restrict__ attn,
    int E)
{
    __shared__ float we_s[EDGE_DIM * HD];  // 8 KB
    __shared__ float at_s[HD];             // attn_vec flattened [h*32+d]
    const int tid = threadIdx.x;
    for (int i = tid; i < EDGE_DIM * HD; i += 256) we_s[i] = We[i];
    if (tid < HD) at_s[tid] = attn[tid];
    __syncthreads();

    const int e = blockIdx.x * 8 + (tid >> 5);
    if (e >= E) return;
    const int ln = tid & 31;

    const int s = __ldg(&snd[e]);
    const int r = __ldg(&rcv[e]);

    float ea = (ln < EDGE_DIM) ? __ldg(&eattr[(size_t)e * EDGE_DIM + ln]) : 0.f;
    float ep0 = 0.f, ep1 = 0.f, ep2 = 0.f, ep3 = 0.f;
#pragma unroll
    for (int k = 0; k < EDGE_DIM; k++) {
        float a = __shfl_sync(0xffffffffu, ea, k);
        ep0 = fmaf(a, we_s[k * HD + ln],      ep0);
        ep1 = fmaf(a, we_s[k * HD + ln + 32], ep1);
        ep2 = fmaf(a, we_s[k * HD + ln + 64], ep2);
        ep3 = fmaf(a, we_s[k * HD + ln + 96], ep3);
    }

    const float* xls = g_xl + (size_t)s * HD;
    const float* xrr = g_xr + (size_t)r * HD;
    float m0 = xls[ln]      + xrr[ln]      + ep0;
    float m1 = xls[ln + 32] + xrr[ln + 32] + ep1;
    float m2 = xls[ln + 64] + xrr[ln + 64] + ep2;
    float m3 = xls[ln + 96] + xrr[ln + 96] + ep3;
    // leaky_relu, slope 0.2
    m0 = fmaxf(m0, 0.f) + 0.2f * fminf(m0, 0.f);
    m1 = fmaxf(m1, 0.f) + 0.2f * fminf(m1, 0.f);
    m2 = fmaxf(m2, 0.f) + 0.2f * fminf(m2, 0.f);
    m3 = fmaxf(m3, 0.f) + 0.2f * fminf(m3, 0.f);

    float p0 = m0 * at_s[ln];
    float p1 = m1 * at_s[32 + ln];
    float p2 = m2 * at_s[64 + ln];
    float p3 = m3 * at_s[96 + ln];
#pragma unroll
    for (int off = 16; off > 0; off >>= 1) {
        p0 += __shfl_xor_sync(0xffffffffu, p0, off);
        p1 += __shfl_xor_sync(0xffffffffu, p1, off);
        p2 += __shfl_xor_sync(0xffffffffu, p2, off);
        p3 += __shfl_xor_sync(0xffffffffu, p3, off);
    }
    if (ln < 4) {
        float lg = (ln == 0) ? p0 : (ln == 1) ? p1 : (ln == 2) ? p2 : p3;
        // No max-subtraction: |logit| is bounded (~12), exp safe in fp32, and
        // exp(l)/sum(exp(l)) == softmax exactly.
        float ev = __expf(lg);
        g_exp[(size_t)e * HEADS + ln] = ev;
        atomicAdd(&g_sum[(size_t)r * HEADS + ln], ev);
    }
}

// ---------------- weighted scatter aggregation ------------------------------
// One warp per edge; lane ln owns 4 contiguous floats (head = ln>>3).
__global__ __launch_bounds__(256) void aggregate_kernel(
    const int* __restrict__ snd,
    const int* __restrict__ rcv,
    int E)
{
    const int e = blockIdx.x * 8 + (threadIdx.x >> 5);
    if (e >= E) return;
    const int ln = threadIdx.x & 31;

    const int s = __ldg(&snd[e]);
    const int r = __ldg(&rcv[e]);

    float a = 0.f;
    if (ln < 4)      a = g_exp[(size_t)e * HEADS + ln];
    else if (ln < 8) a = g_sum[(size_t)r * HEADS + (ln - 4)];

    const int h = ln >> 3;
    float ev = __shfl_sync(0xffffffffu, a, h);
    float sv = __shfl_sync(0xffffffffu, a, h + 4);
    float w  = ev / sv;   // sv >= ev > 0 (this edge contributes to the sum)

    float4 x = *(const float4*)(g_xl + (size_t)s * HD + ln * 4);
    float* dst = g_agg + (size_t)r * HD + ln * 4;
    asm volatile("red.global.add.v4.f32 [%0], {%1, %2, %3, %4};"
                 :: "l"(dst), "f"(x.x * w), "f"(x.y * w), "f"(x.z * w), "f"(x.w * w)
                 : "memory");
}

// ---------------- head mean --------------------------------------------------
__global__ void finalize_kernel(float* __restrict__ out, int N) {
    int i = blockIdx.x * blockDim.x + threadIdx.x;   // over N * 32
    if (i >= N * D_OUT) return;
    int n = i >> 5, d = i & 31;
    const float* a = g_agg + (size_t)n * HD + d;
    out[i] = 0.25f * (a[0] + a[32] + a[64] + a[96]);
}

// ---------------- launch -----------------------------------------------------
extern "C" void kernel_launch(void* const* d_in, const int* in_sizes, int n_in,
                              void* d_out, int out_size)
{
    const float* nodes = (const float*)d_in[0];
    const int*   snd   = (const int*)  d_in[1];
    const int*   rcv   = (const int*)  d_in[2];
    const float* eattr = (const float*)d_in[3];
    // Defend against the n_node scalar being present (size-1 input) or absent.
    int wbase = (in_sizes[4] == 1) ? 5 : 4;
    const float* Wl   = (const float*)d_in[wbase + 0];
    const float* Wr   = (const float*)d_in[wbase + 1];
    const float* We   = (const float*)d_in[wbase + 2];
    const float* attn = (const float*)d_in[wbase + 3];

    const int N = in_sizes[0] / F_IN;
    const int E = in_sizes[1];

    zero_kernel<<<(N * HD + 255) / 256, 256>>>(N * HD, N * HEADS);

    dim3 gg((N + BM - 1) / BM, 4);
    gemm_kernel<<<gg, 256>>>(nodes, Wl, Wr, N);

    edge_score_kernel<<<(E + 7) / 8, 256>>>(snd, rcv, eattr, We, attn, E);
    aggregate_kernel<<<(E + 7) / 8, 256>>>(snd, rcv, E);
    finalize_kernel<<<(N * D_OUT + 255) / 256, 256>>>((float*)d_out, N);
}

// round 2
// speedup vs baseline: 1.5682x; 1.5682x over previous
#include <cuda_runtime.h>
#include <cuda_bf16.h>
#include <cstdint>

// Problem constants (shapes fixed by the dataset)
#define N_NODE   50000
#define N_EDGE   800000
#define F_IN     128
#define EDGE_DIM 16
#define HEADS    4
#define D_OUT    32
#define HD       (HEADS * D_OUT)   // 128

// ---------------- scratch (device globals; no runtime allocation) ----------
__device__ float g_xl [(size_t)N_NODE * HD];     // 25.6 MB
__device__ float g_xr [(size_t)N_NODE * HD];     // 25.6 MB
__device__ float g_sum[(size_t)N_NODE * HEADS];  //  0.8 MB
__device__ float g_agg[(size_t)N_NODE * HD];     // 25.6 MB

// ---------------- zero init --------------------------------------------------
__global__ void zero_kernel(int n_agg, int n_sum) {
    int i = blockIdx.x * blockDim.x + threadIdx.x;
    if (i < n_agg) g_agg[i] = 0.f;
    if (i < n_sum) g_sum[i] = 0.f;
}

// ---------------- projection GEMM: x_l / x_r = nodes @ W ------------------
// C[M,128] = A[M,128] @ W[128,128], two weight matrices via blockIdx.y.
// 64x64 tile, BK=8, 256 threads, 4x4 microtile.
#define BM 64
#define BN 64
#define BK 8
__global__ __launch_bounds__(256) void gemm_kernel(
    const float* __restrict__ A,
    const float* __restrict__ Wl,
    const float* __restrict__ Wr,
    int M)
{
    const int byi = blockIdx.y;                 // 0..3
    const float* B = (byi < 2) ? Wl : Wr;
    float*       C = (byi < 2) ? g_xl : g_xr;
    const int cn0 = (byi & 1) * BN;             // column offset within 128
    const int rm0 = blockIdx.x * BM;

    __shared__ float As[BK][BM + 4];            // transposed, padded
    __shared__ float Bs[BK][BN];

    float acc[4][4];
#pragma unroll
    for (int i = 0; i < 4; i++)
#pragma unroll
        for (int j = 0; j < 4; j++) acc[i][j] = 0.f;

    const int tid = threadIdx.x;
    const int tx = tid & 15;                    // col group
    const int ty = tid >> 4;                    // row group

    const int li = tid * 2;
    const int ar = li / BK, ak = li % BK;       // A load coords
    const int bk = li / BN, bj = li % BN;       // B load coords

    for (int k0 = 0; k0 < F_IN; k0 += BK) {
        float2 av = make_float2(0.f, 0.f);
        if (rm0 + ar < M)
            av = *(const float2*)&A[(size_t)(rm0 + ar) * F_IN + k0 + ak];
        As[ak][ar]     = av.x;
        As[ak + 1][ar] = av.y;
        float2 bv = *(const float2*)&B[(size_t)(k0 + bk) * HD + cn0 + bj];
        Bs[bk][bj]     = bv.x;
        Bs[bk][bj + 1] = bv.y;
        __syncthreads();
#pragma unroll
        for (int k = 0; k < BK; k++) {
            float4 ra = *(const float4*)&As[k][ty * 4];
            float4 rb = *(const float4*)&Bs[k][tx * 4];
            float a_[4] = {ra.x, ra.y, ra.z, ra.w};
            float b_[4] = {rb.x, rb.y, rb.z, rb.w};
#pragma unroll
            for (int i = 0; i < 4; i++)
#pragma unroll
                for (int j = 0; j < 4; j++)
                    acc[i][j] = fmaf(a_[i], b_[j], acc[i][j]);
        }
        __syncthreads();
    }
#pragma unroll
    for (int i = 0; i < 4; i++) {
        int r = rm0 + ty * 4 + i;
        if (r < M) {
            float4 v = make_float4(acc[i][0], acc[i][1], acc[i][2], acc[i][3]);
            *(float4*)&C[(size_t)r * HD + cn0 + tx * 4] = v;
        }
    }
}

// ---------------- fused edge pass: score + UNNORMALIZED aggregation --------
// One warp per edge (persistent grid, warp-strided). Lane ln owns the 4
// contiguous columns 4*ln..4*ln+3; head h = ln>>3 (columns h*32..h*32+31
// map to head h, dims 0..31). Per-head logit via 8-lane segmented reduce.
// Accumulates exp_e * x_l[s] into g_agg and exp_e into g_sum; normalization
// (divide by sum+1e-8) happens in finalize. Algebraically identical to the
// reference softmax-then-weighted-sum.
__global__ __launch_bounds__(256) void edge_fused_kernel(
    const int*   __restrict__ snd,
    const int*   __restrict__ rcv,
    const float* __restrict__ eattr,
    const float* __restrict__ We,
    const float* __restrict__ attn,
    int E)
{
    __shared__ float we_s[EDGE_DIM * HD];  // 8 KB
    __shared__ float at_s[HD];
    const int tid = threadIdx.x;
    for (int i = tid; i < EDGE_DIM * HD; i += 256) we_s[i] = We[i];
    if (tid < HD) at_s[tid] = attn[tid];
    __syncthreads();

    const int ln = tid & 31;
    const int c0 = ln * 4;                  // my 4 columns
    const int h  = ln >> 3;                 // my head

    // preload per-lane constants
    const float4 wv[EDGE_DIM] = {};         // (placeholder removed below)
    (void)wv;
    float4 at4 = *(const float4*)&at_s[c0];

    const int warps_total = gridDim.x * (blockDim.x >> 5);
    const int warp_id = blockIdx.x * (blockDim.x >> 5) + (tid >> 5);

    for (int e = warp_id; e < E; e += warps_total) {
        const int s = __ldg(&snd[e]);
        const int r = __ldg(&rcv[e]);

        // edge projection for my 4 columns
        float ea = (ln < EDGE_DIM) ? __ldg(&eattr[(size_t)e * EDGE_DIM + ln]) : 0.f;
        float4 ep = make_float4(0.f, 0.f, 0.f, 0.f);
#pragma unroll
        for (int k = 0; k < EDGE_DIM; k++) {
            float a = __shfl_sync(0xffffffffu, ea, k);
            float4 w = *(const float4*)&we_s[k * HD + c0];
            ep.x = fmaf(a, w.x, ep.x);
            ep.y = fmaf(a, w.y, ep.y);
            ep.z = fmaf(a, w.z, ep.z);
            ep.w = fmaf(a, w.w, ep.w);
        }

        float4 xl = *(const float4*)(g_xl + (size_t)s * HD + c0);
        float4 xr = *(const float4*)(g_xr + (size_t)r * HD + c0);

        float m0 = xl.x + xr.x + ep.x;
        float m1 = xl.y + xr.y + ep.y;
        float m2 = xl.z + xr.z + ep.z;
        float m3 = xl.w + xr.w + ep.w;
        // leaky_relu slope 0.2
        m0 = fmaxf(m0, 0.f) + 0.2f * fminf(m0, 0.f);
        m1 = fmaxf(m1, 0.f) + 0.2f * fminf(m1, 0.f);
        m2 = fmaxf(m2, 0.f) + 0.2f * fminf(m2, 0.f);
        m3 = fmaxf(m3, 0.f) + 0.2f * fminf(m3, 0.f);

        float p = fmaf(m0, at4.x, fmaf(m1, at4.y, fmaf(m2, at4.z, m3 * at4.w)));
        // segmented reduce over my 8-lane head group
        p += __shfl_xor_sync(0xffffffffu, p, 4);
        p += __shfl_xor_sync(0xffffffffu, p, 2);
        p += __shfl_xor_sync(0xffffffffu, p, 1);

        // No max-subtraction: |logit| bounded (~12), exp safe in fp32.
        float ev = __expf(p);

        float* dst = g_agg + (size_t)r * HD + c0;
        asm volatile("red.global.add.v4.f32 [%0], {%1, %2, %3, %4};"
                     :: "l"(dst), "f"(xl.x * ev), "f"(xl.y * ev),
                        "f"(xl.z * ev), "f"(xl.w * ev)
                     : "memory");
        if ((ln & 7) == 0)
            atomicAdd(&g_sum[(size_t)r * HEADS + h], ev);
    }
}

// ---------------- finalize: normalize + head mean ---------------------------
__global__ void finalize_kernel(float* __restrict__ out, int N) {
    int i = blockIdx.x * blockDim.x + threadIdx.x;   // over N * 32
    if (i >= N * D_OUT) return;
    int n = i >> 5, d = i & 31;
    const float* a = g_agg + (size_t)n * HD + d;
    const float* sm = g_sum + (size_t)n * HEADS;
    float v = a[0]  / (sm[0] + 1e-8f)
            + a[32] / (sm[1] + 1e-8f)
            + a[64] / (sm[2] + 1e-8f)
            + a[96] / (sm[3] + 1e-8f);
    out[i] = 0.25f * v;
}

// ---------------- launch -----------------------------------------------------
extern "C" void kernel_launch(void* const* d_in, const int* in_sizes, int n_in,
                              void* d_out, int out_size)
{
    const float* nodes = (const float*)d_in[0];
    const int*   snd   = (const int*)  d_in[1];
    const int*   rcv   = (const int*)  d_in[2];
    const float* eattr = (const float*)d_in[3];
    // Defend against the n_node scalar being present (size-1 input) or absent.
    int wbase = (in_sizes[4] == 1) ? 5 : 4;
    const float* Wl   = (const float*)d_in[wbase + 0];
    const float* Wr   = (const float*)d_in[wbase + 1];
    const float* We   = (const float*)d_in[wbase + 2];
    const float* attn = (const float*)d_in[wbase + 3];

    const int N = in_sizes[0] / F_IN;
    const int E = in_sizes[1];

    zero_kernel<<<(N * HD + 255) / 256, 256>>>(N * HD, N * HEADS);

    dim3 gg((N + BM - 1) / BM, 4);
    gemm_kernel<<<gg, 256>>>(nodes, Wl, Wr, N);

    // persistent grid: 8 blocks/SM * 148 SMs
    edge_fused_kernel<<<1184, 256>>>(snd, rcv, eattr, We, attn, E);
    finalize_kernel<<<(N * D_OUT + 255) / 256, 256>>>((float*)d_out, N);
}